// round 1
// baseline (speedup 1.0000x reference)
#include <cuda_runtime.h>
#include <cuda_bf16.h>
#include <cstddef>

#define NN 100000
#define EE 1600000
#define DD 128

// ---------------- scratch (device globals; no allocation allowed) ----------
__device__ float g_agg[(size_t)NN * DD];
__device__ float g_h1[(size_t)NN * DD];
__device__ float g_h2[(size_t)NN * DD];
__device__ float g_cnt[NN];
__device__ float g_inv[NN];
__device__ float g_Wc[3][256 * DD];
__device__ int   g_is64;

// ---------------- int64/int32 edge-index detection -------------------------
// Reference declares int64, but JAX without x64 silently emits int32.
// Interpreting int32 data as int64 packs two random indices per word ->
// value >= 2^32 with overwhelming probability. Scan 256 words.
__global__ void detect_idx_kernel(const void* ei, int e, int n) {
    if (threadIdx.x != 0 || blockIdx.x != 0) return;
    const long long* p = (const long long*)ei;
    int is64 = 1;
    int lim = (e < 256) ? e : 256;
    for (int i = 0; i < lim; i++) {
        long long v = p[i];
        if (v < 0 || v >= n) { is64 = 0; break; }
    }
    g_is64 = is64;
}

__device__ __forceinline__ int load_idx(const void* ei, int e, int i, int part, int is64) {
    if (is64) return (int)(((const long long*)ei)[(size_t)part * e + i]);
    return ((const int*)ei)[(size_t)part * e + i];
}

// ---------------- degree count + inverse ------------------------------------
__global__ void count_kernel(const void* __restrict__ ei, int e, float* __restrict__ cnt) {
    int i = blockIdx.x * blockDim.x + threadIdx.x;
    if (i >= e) return;
    int dst = load_idx(ei, e, i, 1, g_is64);
    atomicAdd(&cnt[dst], 1.0f);
}

__global__ void inv_kernel(const float* __restrict__ cnt, float* __restrict__ inv, int n) {
    int i = blockIdx.x * blockDim.x + threadIdx.x;
    if (i < n) inv[i] = 1.0f / fmaxf(cnt[i], 1.0f);
}

// ---------------- weight concat: Wc[k][j] = (k<128 ? Wl[j][k] : Wr[j][k-128]) ----
__global__ void build_wc_kernel(const float* __restrict__ Wl, const float* __restrict__ Wr,
                                float* __restrict__ Wc) {
    int j = threadIdx.x;      // 0..127
    int k = blockIdx.x;       // 0..255
    Wc[k * DD + j] = (k < DD) ? Wl[j * DD + k] : Wr[j * DD + (k - DD)];
}

// ---------------- scatter-add: one warp per edge ----------------------------
__global__ void scatter_kernel(const float* __restrict__ xin, const void* __restrict__ ei,
                               float* __restrict__ agg, int e) {
    int gw = (blockIdx.x * blockDim.x + threadIdx.x) >> 5;
    int lane = threadIdx.x & 31;
    if (gw >= e) return;
    int is64 = g_is64;
    int src = load_idx(ei, e, gw, 0, is64);
    int dst = load_idx(ei, e, gw, 1, is64);
    float4 v = *(const float4*)(xin + (size_t)src * DD + lane * 4);
    float* a = agg + (size_t)dst * DD + lane * 4;
    atomicAdd(a + 0, v.x);
    atomicAdd(a + 1, v.y);
    atomicAdd(a + 2, v.z);
    atomicAdd(a + 3, v.w);
}

// ---------------- fused GEMM: out = [agg*inv | xin] @ Wc + b (+relu) --------
// Block tile: 64 rows x 128 cols, K=256 in steps of 16. 256 threads,
// per-thread 8x4 register tile. A_sh stored transposed [k][row].
__global__ __launch_bounds__(256) void gemm_kernel(
    const float* __restrict__ agg, const float* __restrict__ xin,
    const float* __restrict__ inv, const float* __restrict__ Wc,
    const float* __restrict__ bias, float* __restrict__ out,
    int n, int do_relu)
{
    __shared__ float A_sh[16][64];
    __shared__ float W_sh[16][128];

    const int tid  = threadIdx.x;
    const int lane = tid & 31;
    const int warp = tid >> 5;
    const int tcol = lane * 4;   // 4 output cols
    const int trow = warp * 8;   // 8 output rows
    const int brow = blockIdx.x * 64;

    // A-tile load mapping: thread loads float4 along k for one row
    const int arow = tid & 63;
    const int ak0  = (tid >> 6) * 4;   // 0,4,8,12
    const int grow = brow + arow;
    const bool arow_ok = (grow < n);

    float acc[8][4];
    #pragma unroll
    for (int r = 0; r < 8; r++)
        #pragma unroll
        for (int c = 0; c < 4; c++) acc[r][c] = 0.0f;

    for (int kb = 0; kb < 256; kb += 16) {
        // global loads for this stage
        float4 av = make_float4(0.f, 0.f, 0.f, 0.f);
        if (arow_ok) {
            if (kb < 128) {
                av = *(const float4*)(agg + (size_t)grow * DD + kb + ak0);
                float s = inv[grow];
                av.x *= s; av.y *= s; av.z *= s; av.w *= s;
            } else {
                av = *(const float4*)(xin + (size_t)grow * DD + (kb - 128) + ak0);
            }
        }
        // W tile: 16x128 = 512 float4, 2 per thread
        float4 wv0 = *(const float4*)(Wc + (size_t)(kb + (tid >> 5)) * DD + (tid & 31) * 4);
        float4 wv1 = *(const float4*)(Wc + (size_t)(kb + 8 + (tid >> 5)) * DD + (tid & 31) * 4);

        __syncthreads();
        A_sh[ak0 + 0][arow] = av.x;
        A_sh[ak0 + 1][arow] = av.y;
        A_sh[ak0 + 2][arow] = av.z;
        A_sh[ak0 + 3][arow] = av.w;
        *(float4*)&W_sh[tid >> 5][(tid & 31) * 4]       = wv0;
        *(float4*)&W_sh[8 + (tid >> 5)][(tid & 31) * 4] = wv1;
        __syncthreads();

        #pragma unroll
        for (int k = 0; k < 16; k++) {
            float4 w  = *(const float4*)&W_sh[k][tcol];
            float4 a0 = *(const float4*)&A_sh[k][trow];
            float4 a1 = *(const float4*)&A_sh[k][trow + 4];
            float ar[8] = {a0.x, a0.y, a0.z, a0.w, a1.x, a1.y, a1.z, a1.w};
            #pragma unroll
            for (int r = 0; r < 8; r++) {
                acc[r][0] += ar[r] * w.x;
                acc[r][1] += ar[r] * w.y;
                acc[r][2] += ar[r] * w.z;
                acc[r][3] += ar[r] * w.w;
            }
        }
    }

    float4 bv = *(const float4*)(bias + tcol);
    #pragma unroll
    for (int r = 0; r < 8; r++) {
        int row = brow + trow + r;
        if (row < n) {
            float4 o;
            o.x = acc[r][0] + bv.x;
            o.y = acc[r][1] + bv.y;
            o.z = acc[r][2] + bv.z;
            o.w = acc[r][3] + bv.w;
            if (do_relu) {
                o.x = fmaxf(o.x, 0.f); o.y = fmaxf(o.y, 0.f);
                o.z = fmaxf(o.z, 0.f); o.w = fmaxf(o.w, 0.f);
            }
            *(float4*)(out + (size_t)row * DD + tcol) = o;
        }
    }
}

// ---------------- host orchestration ---------------------------------------
extern "C" void kernel_launch(void* const* d_in, const int* in_sizes, int n_in,
                              void* d_out, int out_size) {
    const float* x   = (const float*)d_in[0];
    const void*  ei  = d_in[1];
    const float* Wl1 = (const float*)d_in[2];
    const float* Wr1 = (const float*)d_in[3];
    const float* b1  = (const float*)d_in[4];
    const float* Wl2 = (const float*)d_in[5];
    const float* Wr2 = (const float*)d_in[6];
    const float* b2  = (const float*)d_in[7];
    const float* Wl3 = (const float*)d_in[8];
    const float* Wr3 = (const float*)d_in[9];
    const float* b3  = (const float*)d_in[10];

    const int n = in_sizes[0] / DD;
    const int e = in_sizes[1] / 2;
    float* out = (float*)d_out;

    float *agg, *h1, *h2, *cnt, *inv, *wc;
    cudaGetSymbolAddress((void**)&agg, g_agg);
    cudaGetSymbolAddress((void**)&h1,  g_h1);
    cudaGetSymbolAddress((void**)&h2,  g_h2);
    cudaGetSymbolAddress((void**)&cnt, g_cnt);
    cudaGetSymbolAddress((void**)&inv, g_inv);
    cudaGetSymbolAddress((void**)&wc,  g_Wc);

    const size_t feat_bytes = (size_t)n * DD * sizeof(float);
    const int thr = 256;
    const int eb   = (e + thr - 1) / thr;
    const int nb   = (n + thr - 1) / thr;
    const int sb   = (int)(((long long)e * 32 + thr - 1) / thr);
    const int gemb = (n + 63) / 64;

    // graph-invariant prep
    detect_idx_kernel<<<1, 1>>>(ei, e, n);
    cudaMemsetAsync(cnt, 0, (size_t)n * sizeof(float));
    count_kernel<<<eb, thr>>>(ei, e, cnt);
    inv_kernel<<<nb, thr>>>(cnt, inv, n);
    build_wc_kernel<<<256, DD>>>(Wl1, Wr1, wc + 0 * 256 * DD);
    build_wc_kernel<<<256, DD>>>(Wl2, Wr2, wc + 1 * 256 * DD);
    build_wc_kernel<<<256, DD>>>(Wl3, Wr3, wc + 2 * 256 * DD);

    // layer 1
    cudaMemsetAsync(agg, 0, feat_bytes);
    scatter_kernel<<<sb, thr>>>(x, ei, agg, e);
    gemm_kernel<<<gemb, 256>>>(agg, x, inv, wc + 0 * 256 * DD, b1, h1, n, 1);

    // layer 2
    cudaMemsetAsync(agg, 0, feat_bytes);
    scatter_kernel<<<sb, thr>>>(h1, ei, agg, e);
    gemm_kernel<<<gemb, 256>>>(agg, h1, inv, wc + 1 * 256 * DD, b2, h2, n, 1);

    // layer 3
    cudaMemsetAsync(agg, 0, feat_bytes);
    scatter_kernel<<<sb, thr>>>(h2, ei, agg, e);
    gemm_kernel<<<gemb, 256>>>(agg, h2, inv, wc + 2 * 256 * DD, b3, out, n, 0);
}

// round 3
// speedup vs baseline: 2.6159x; 2.6159x over previous
#include <cuda_runtime.h>
#include <cstddef>

#define NN 100000
#define EE 1600000
#define DD 128

// ---------------- scratch (device globals; no allocation allowed) ----------
__device__ float g_agg[(size_t)NN * DD];
__device__ float g_h1[(size_t)NN * DD];
__device__ float g_h2[(size_t)NN * DD];
__device__ float g_inv[NN];
__device__ float g_Wc[3][256 * DD];
__device__ int   g_deg[NN];
__device__ int   g_rowptr[NN + 1];
__device__ int   g_cursor[NN];
__device__ int   g_col[EE];
__device__ int   g_bsums[256];
__device__ int   g_is64;

// ---------------- f32x2 packed-FMA helpers ---------------------------------
__device__ __forceinline__ unsigned long long pack2(float x, float y) {
    unsigned long long r;
    asm("mov.b64 %0, {%1, %2};" : "=l"(r) : "f"(x), "f"(y));
    return r;
}
__device__ __forceinline__ void unpack2(unsigned long long v, float& x, float& y) {
    asm("mov.b64 {%0, %1}, %2;" : "=f"(x), "=f"(y) : "l"(v));
}
__device__ __forceinline__ void ffma2(unsigned long long& d,
                                      unsigned long long a,
                                      unsigned long long b) {
    asm("fma.rn.f32x2 %0, %1, %2, %0;" : "+l"(d) : "l"(a), "l"(b));
}

// ---------------- int64/int32 edge-index detection -------------------------
__global__ void detect_idx_kernel(const void* ei, int e, int n) {
    if (threadIdx.x != 0 || blockIdx.x != 0) return;
    const long long* p = (const long long*)ei;
    int is64 = 1;
    int lim = (e < 256) ? e : 256;
    for (int i = 0; i < lim; i++) {
        long long v = p[i];
        if (v < 0 || v >= n) { is64 = 0; break; }
    }
    g_is64 = is64;
}

__device__ __forceinline__ int load_idx(const void* ei, int e, int i, int part, int is64) {
    if (is64) return (int)(((const long long*)ei)[(size_t)part * e + i]);
    return ((const int*)ei)[(size_t)part * e + i];
}

// ---------------- CSR construction ------------------------------------------
__global__ void hist_kernel(const void* __restrict__ ei, int e, int* __restrict__ deg) {
    int i = blockIdx.x * blockDim.x + threadIdx.x;
    if (i >= e) return;
    int dst = load_idx(ei, e, i, 1, g_is64);
    atomicAdd(&deg[dst], 1);
}

// block-level exclusive scan over 1024-element chunks
__global__ void scanA_kernel(const int* __restrict__ deg, int* __restrict__ rp,
                             int* __restrict__ bsums, int n) {
    __shared__ int wsum[8];
    int t = threadIdx.x;
    int base = blockIdx.x * 1024;
    int idx = base + t * 4;
    int v[4];
    #pragma unroll
    for (int j = 0; j < 4; j++) v[j] = (idx + j < n) ? deg[idx + j] : 0;
    int tsum = v[0] + v[1] + v[2] + v[3];
    int lane = t & 31, w = t >> 5;
    int inc = tsum;
    #pragma unroll
    for (int d = 1; d < 32; d <<= 1) {
        int x = __shfl_up_sync(0xFFFFFFFFu, inc, d);
        if (lane >= d) inc += x;
    }
    if (lane == 31) wsum[w] = inc;
    __syncthreads();
    if (t == 0) {
        int a = 0;
        #pragma unroll
        for (int i = 0; i < 8; i++) { int tmp = wsum[i]; wsum[i] = a; a += tmp; }
        bsums[blockIdx.x] = a;
    }
    __syncthreads();
    int run = inc - tsum + wsum[w];
    #pragma unroll
    for (int j = 0; j < 4; j++) {
        if (idx + j < n) rp[idx + j] = run;
        run += v[j];
    }
}

__global__ void scanB_kernel(int* __restrict__ bsums, int nb) {
    __shared__ int sh[256];
    int t = threadIdx.x;
    sh[t] = (t < nb) ? bsums[t] : 0;
    __syncthreads();
    if (t == 0) {
        int a = 0;
        for (int i = 0; i < nb; i++) { int tmp = sh[i]; sh[i] = a; a += tmp; }
    }
    __syncthreads();
    if (t < nb) bsums[t] = sh[t];
}

__global__ void scanC_kernel(int* __restrict__ rp, int* __restrict__ cursor,
                             const int* __restrict__ bsums, const int* __restrict__ deg,
                             float* __restrict__ inv, int n, int e) {
    int i = blockIdx.x * blockDim.x + threadIdx.x;
    if (i >= n) return;
    int v = rp[i] + bsums[i >> 10];
    rp[i] = v;
    cursor[i] = v;
    inv[i] = 1.0f / fmaxf((float)deg[i], 1.0f);
    if (i == 0) rp[n] = e;
}

__global__ void fill_kernel(const void* __restrict__ ei, int e,
                            int* __restrict__ cursor, int* __restrict__ col) {
    int i = blockIdx.x * blockDim.x + threadIdx.x;
    if (i >= e) return;
    int is64 = g_is64;
    int src = load_idx(ei, e, i, 0, is64);
    int dst = load_idx(ei, e, i, 1, is64);
    int pos = atomicAdd(&cursor[dst], 1);
    col[pos] = src;
}

// ---------------- weight concat: Wc[k][j] = (k<128 ? Wl[j][k] : Wr[j][k-128]) ----
__global__ void build_wc_kernel(const float* __restrict__ Wl, const float* __restrict__ Wr,
                                float* __restrict__ Wc) {
    int j = threadIdx.x;
    int k = blockIdx.x;
    Wc[k * DD + j] = (k < DD) ? Wl[j * DD + k] : Wr[j * DD + (k - DD)];
}

// ---------------- CSR gather mean: one warp per node ------------------------
__global__ __launch_bounds__(256) void gather_kernel(
    const float* __restrict__ xin, const int* __restrict__ rp,
    const int* __restrict__ col, const float* __restrict__ inv,
    float* __restrict__ agg, int n)
{
    int node = (blockIdx.x * blockDim.x + threadIdx.x) >> 5;
    int lane = threadIdx.x & 31;
    if (node >= n) return;
    int beg = rp[node], end = rp[node + 1];
    const float4* xv = (const float4*)xin;
    float4 acc = make_float4(0.f, 0.f, 0.f, 0.f);
    int j = beg;
    for (; j + 4 <= end; j += 4) {
        int s0 = __ldg(&col[j + 0]);
        int s1 = __ldg(&col[j + 1]);
        int s2 = __ldg(&col[j + 2]);
        int s3 = __ldg(&col[j + 3]);
        float4 v0 = __ldg(&xv[(size_t)s0 * 32 + lane]);
        float4 v1 = __ldg(&xv[(size_t)s1 * 32 + lane]);
        float4 v2 = __ldg(&xv[(size_t)s2 * 32 + lane]);
        float4 v3 = __ldg(&xv[(size_t)s3 * 32 + lane]);
        acc.x += v0.x + v1.x + v2.x + v3.x;
        acc.y += v0.y + v1.y + v2.y + v3.y;
        acc.z += v0.z + v1.z + v2.z + v3.z;
        acc.w += v0.w + v1.w + v2.w + v3.w;
    }
    for (; j < end; j++) {
        int s = __ldg(&col[j]);
        float4 v = __ldg(&xv[(size_t)s * 32 + lane]);
        acc.x += v.x; acc.y += v.y; acc.z += v.z; acc.w += v.w;
    }
    float sc = inv[node];
    acc.x *= sc; acc.y *= sc; acc.z *= sc; acc.w *= sc;
    ((float4*)agg)[(size_t)node * 32 + lane] = acc;
}

// ---------------- fused GEMM: out = [mean | xin] @ Wc + b (+relu) -----------
// 128x128 block tile, K=256 in 16-wide stages, 256 threads.
// Per-thread micro-tile: 16 rows (as 8 row-pairs in b64 regs) x 4 cols,
// inner product via packed fma.rn.f32x2 (FFMA2).
__global__ __launch_bounds__(256) void gemm_kernel(
    const float* __restrict__ mean, const float* __restrict__ xin,
    const float* __restrict__ Wc, const float* __restrict__ bias,
    float* __restrict__ out, int n, int do_relu)
{
    __shared__ __align__(16) float A_sh[16][128];
    __shared__ __align__(16) float W_sh[16][128];

    const int tid  = threadIdx.x;
    const int lane = tid & 31;
    const int warp = tid >> 5;          // 0..7 -> 16 rows each
    const int brow = blockIdx.x * 128;

    // A loader: thread covers row (tid&127), k-span 8 starting at (tid>>7)*8
    const int arow = tid & 127;
    const int ak0  = (tid >> 7) * 8;    // 0 or 8
    const int grow = brow + arow;
    const bool arow_ok = (grow < n);

    unsigned long long acc[8][4];
    #pragma unroll
    for (int p = 0; p < 8; p++)
        #pragma unroll
        for (int c = 0; c < 4; c++) acc[p][c] = 0ull;

    for (int kb = 0; kb < 256; kb += 16) {
        // global prefetch into registers
        float4 av0 = make_float4(0.f, 0.f, 0.f, 0.f);
        float4 av1 = av0;
        if (arow_ok) {
            const float* src = (kb < 128) ? (mean + (size_t)grow * DD + kb)
                                          : (xin  + (size_t)grow * DD + (kb - 128));
            av0 = *(const float4*)(src + ak0);
            av1 = *(const float4*)(src + ak0 + 4);
        }
        const int wk0 = (2 * tid) >> 5;         // 0..15
        const int wc0 = (2 * tid) & 31;         // float4 index in row
        float4 wv0 = *(const float4*)(Wc + (size_t)(kb + wk0) * DD + wc0 * 4);
        const int wk1 = (2 * tid + 1) >> 5;
        const int wc1 = (2 * tid + 1) & 31;
        float4 wv1 = *(const float4*)(Wc + (size_t)(kb + wk1) * DD + wc1 * 4);

        __syncthreads();
        A_sh[ak0 + 0][arow] = av0.x;
        A_sh[ak0 + 1][arow] = av0.y;
        A_sh[ak0 + 2][arow] = av0.z;
        A_sh[ak0 + 3][arow] = av0.w;
        A_sh[ak0 + 4][arow] = av1.x;
        A_sh[ak0 + 5][arow] = av1.y;
        A_sh[ak0 + 6][arow] = av1.z;
        A_sh[ak0 + 7][arow] = av1.w;
        *(float4*)&W_sh[wk0][wc0 * 4] = wv0;
        *(float4*)&W_sh[wk1][wc1 * 4] = wv1;
        __syncthreads();

        #pragma unroll
        for (int k = 0; k < 16; k++) {
            float4 b4 = *(const float4*)&W_sh[k][lane * 4];
            unsigned long long bb0 = pack2(b4.x, b4.x);
            unsigned long long bb1 = pack2(b4.y, b4.y);
            unsigned long long bb2 = pack2(b4.z, b4.z);
            unsigned long long bb3 = pack2(b4.w, b4.w);
            const unsigned long long* ap =
                (const unsigned long long*)&A_sh[k][warp * 16];
            #pragma unroll
            for (int p = 0; p < 8; p++) {
                unsigned long long a2 = ap[p];   // LDS.64 broadcast (row pair)
                ffma2(acc[p][0], a2, bb0);
                ffma2(acc[p][1], a2, bb1);
                ffma2(acc[p][2], a2, bb2);
                ffma2(acc[p][3], a2, bb3);
            }
        }
    }

    float4 bv = *(const float4*)(bias + lane * 4);
    #pragma unroll
    for (int p = 0; p < 8; p++) {
        float lo0, hi0, lo1, hi1, lo2, hi2, lo3, hi3;
        unpack2(acc[p][0], lo0, hi0);
        unpack2(acc[p][1], lo1, hi1);
        unpack2(acc[p][2], lo2, hi2);
        unpack2(acc[p][3], lo3, hi3);
        int r0 = brow + warp * 16 + 2 * p;
        if (r0 < n) {
            float4 o = make_float4(lo0 + bv.x, lo1 + bv.y, lo2 + bv.z, lo3 + bv.w);
            if (do_relu) {
                o.x = fmaxf(o.x, 0.f); o.y = fmaxf(o.y, 0.f);
                o.z = fmaxf(o.z, 0.f); o.w = fmaxf(o.w, 0.f);
            }
            *(float4*)(out + (size_t)r0 * DD + lane * 4) = o;
        }
        if (r0 + 1 < n) {
            float4 o = make_float4(hi0 + bv.x, hi1 + bv.y, hi2 + bv.z, hi3 + bv.w);
            if (do_relu) {
                o.x = fmaxf(o.x, 0.f); o.y = fmaxf(o.y, 0.f);
                o.z = fmaxf(o.z, 0.f); o.w = fmaxf(o.w, 0.f);
            }
            *(float4*)(out + (size_t)(r0 + 1) * DD + lane * 4) = o;
        }
    }
}

// ---------------- host orchestration ---------------------------------------
extern "C" void kernel_launch(void* const* d_in, const int* in_sizes, int n_in,
                              void* d_out, int out_size) {
    const float* x   = (const float*)d_in[0];
    const void*  ei  = d_in[1];
    const float* Wl1 = (const float*)d_in[2];
    const float* Wr1 = (const float*)d_in[3];
    const float* b1  = (const float*)d_in[4];
    const float* Wl2 = (const float*)d_in[5];
    const float* Wr2 = (const float*)d_in[6];
    const float* b2  = (const float*)d_in[7];
    const float* Wl3 = (const float*)d_in[8];
    const float* Wr3 = (const float*)d_in[9];
    const float* b3  = (const float*)d_in[10];

    const int n = in_sizes[0] / DD;
    const int e = in_sizes[1] / 2;
    float* out = (float*)d_out;

    float *agg, *h1, *h2, *inv, *wc;
    int *deg, *rp, *cursor, *col, *bsums;
    cudaGetSymbolAddress((void**)&agg,    g_agg);
    cudaGetSymbolAddress((void**)&h1,     g_h1);
    cudaGetSymbolAddress((void**)&h2,     g_h2);
    cudaGetSymbolAddress((void**)&inv,    g_inv);
    cudaGetSymbolAddress((void**)&wc,     g_Wc);
    cudaGetSymbolAddress((void**)&deg,    g_deg);
    cudaGetSymbolAddress((void**)&rp,     g_rowptr);
    cudaGetSymbolAddress((void**)&cursor, g_cursor);
    cudaGetSymbolAddress((void**)&col,    g_col);
    cudaGetSymbolAddress((void**)&bsums,  g_bsums);

    const int thr = 256;
    const int eb   = (e + thr - 1) / thr;
    const int nb   = (n + thr - 1) / thr;
    const int scb  = (n + 1023) / 1024;              // scan chunks
    const int gab  = (n * 32 + thr - 1) / thr;       // gather blocks (warp/node)
    const int gemb = (n + 127) / 128;

    // --- CSR build (graph-invariant within a launch) ---
    detect_idx_kernel<<<1, 1>>>(ei, e, n);
    cudaMemsetAsync(deg, 0, (size_t)n * sizeof(int));
    hist_kernel<<<eb, thr>>>(ei, e, deg);
    scanA_kernel<<<scb, 256>>>(deg, rp, bsums, n);
    scanB_kernel<<<1, 256>>>(bsums, scb);
    scanC_kernel<<<nb, thr>>>(rp, cursor, bsums, deg, inv, n, e);
    fill_kernel<<<eb, thr>>>(ei, e, cursor, col);

    build_wc_kernel<<<256, DD>>>(Wl1, Wr1, wc + 0 * 256 * DD);
    build_wc_kernel<<<256, DD>>>(Wl2, Wr2, wc + 1 * 256 * DD);
    build_wc_kernel<<<256, DD>>>(Wl3, Wr3, wc + 2 * 256 * DD);

    // --- layer 1 ---
    gather_kernel<<<gab, thr>>>(x, rp, col, inv, agg, n);
    gemm_kernel<<<gemb, 256>>>(agg, x, wc + 0 * 256 * DD, b1, h1, n, 1);
    // --- layer 2 ---
    gather_kernel<<<gab, thr>>>(h1, rp, col, inv, agg, n);
    gemm_kernel<<<gemb, 256>>>(agg, h1, wc + 1 * 256 * DD, b2, h2, n, 1);
    // --- layer 3 ---
    gather_kernel<<<gab, thr>>>(h2, rp, col, inv, agg, n);
    gemm_kernel<<<gemb, 256>>>(agg, h2, wc + 2 * 256 * DD, b3, out, n, 0);
}